// round 1
// baseline (speedup 1.0000x reference)
#include <cuda_runtime.h>

// Energy distance, B=16, N=M=256, D=128, fp32.
// Per (batch, dim): sort both columns, closed-form pairwise L1 sums.

#define EB 16
#define EN 256
#define ED 128

__global__ void ed_init_out(float* out) {
    if (threadIdx.x < EB) out[threadIdx.x] = 0.0f;
}

__global__ __launch_bounds__(256) void ed_kernel(
    const float* __restrict__ x1,
    const float* __restrict__ x2,
    float* __restrict__ out)
{
    __shared__ float s1[EN];       // x1 column, sorted in place
    __shared__ float s2[EN];       // x2 column, sorted in place
    __shared__ float pb[EN + 1];   // exclusive prefix of sorted s2
    __shared__ float red[EN];      // scan temp / reduction buffer

    const int d = blockIdx.x;   // dimension 0..127
    const int b = blockIdx.y;   // batch 0..15
    const int t = threadIdx.x;  // 0..255

    // Strided column loads (L2-resident; total footprint 4 MB)
    const size_t base = ((size_t)b * EN + t) * ED + d;
    s1[t] = x1[base];
    s2[t] = x2[base];
    __syncthreads();

    // Bitonic sort both arrays simultaneously (ascending).
    // Each pair (t, t^j) handled by the lower thread only -> race-free.
    #pragma unroll 1
    for (int k = 2; k <= EN; k <<= 1) {
        #pragma unroll 1
        for (int j = k >> 1; j > 0; j >>= 1) {
            const int p = t ^ j;
            if (p > t) {
                const bool asc = ((t & k) == 0);
                float u = s1[t], v = s1[p];
                if ((u > v) == asc) { s1[t] = v; s1[p] = u; }
                u = s2[t]; v = s2[p];
                if ((u > v) == asc) { s2[t] = v; s2[p] = u; }
            }
            __syncthreads();
        }
    }

    // Inclusive scan of sorted s2 (Hillis-Steele), then shift to exclusive pb.
    red[t] = s2[t];
    __syncthreads();
    #pragma unroll 1
    for (int off = 1; off < EN; off <<= 1) {
        const float add = (t >= off) ? red[t - off] : 0.0f;
        __syncthreads();
        red[t] += add;
        __syncthreads();
    }
    pb[t + 1] = red[t];
    if (t == 0) pb[0] = 0.0f;
    __syncthreads();

    const float Ptot = pb[EN];

    // Cross term: a = s1[t] (sorted set == original set).
    // r = count of s2[j] <= a  (upper_bound). Ties contribute 0 either way.
    const float a = s1[t];
    int lo = 0, hi = EN;
    #pragma unroll 1
    while (lo < hi) {
        const int mid = (lo + hi) >> 1;
        if (s2[mid] <= a) lo = mid + 1; else hi = mid;
    }
    const float cross = a * (float)(2 * lo - EN) + Ptot - 2.0f * pb[lo];

    // Same-term closed forms on sorted values:
    // full double-sum = 2 * sum_k (2k - (M-1)) * v_(k); combined with the -0.5
    // weight this is exactly -(2t-255)*(s1[t]+s2[t]) summed over t.
    const float w = (float)(2 * t - (EN - 1));
    const float tot = cross - w * (s1[t] + s2[t]);

    // Block tree reduction.
    __syncthreads();
    red[t] = tot;
    __syncthreads();
    #pragma unroll 1
    for (int s = EN / 2; s > 0; s >>= 1) {
        if (t < s) red[t] += red[t + s];
        __syncthreads();
    }

    if (t == 0) {
        // mean normalization: / (N*M) = / 65536
        atomicAdd(out + b, red[0] * (1.0f / (float)(EN * EN)));
    }
}

extern "C" void kernel_launch(void* const* d_in, const int* in_sizes, int n_in,
                              void* d_out, int out_size)
{
    const float* x1 = (const float*)d_in[0];
    const float* x2 = (const float*)d_in[1];
    float* out = (float*)d_out;

    ed_init_out<<<1, 32>>>(out);
    dim3 grid(ED, EB);
    ed_kernel<<<grid, 256>>>(x1, x2, out);
}

// round 2
// speedup vs baseline: 2.3593x; 2.3593x over previous
#include <cuda_runtime.h>

// Energy distance, B=16, N=M=256, D=128, fp32.
// Per (batch, dim): warp-register bitonic sort (8 elems/thread),
// closed-form pairwise L1 sums via prefix sums + binary search.

#define EB 16
#define EN 256
#define ED 128
#define FULL_MASK 0xFFFFFFFFu

// Padded physical index: stride 9 per lane-group -> bank-conflict-free
// for the i = 8*lane + r access pattern (gcd(9,32)=1).
__device__ __forceinline__ int phys(int i) { return i + (i >> 3); }

__device__ __forceinline__ void warp_sort256(float v[8], int lane) {
    #pragma unroll
    for (int k = 2; k <= 256; k <<= 1) {
        // Cross-lane stages: j >= 8 -> shfl.xor with mask j/8.
        #pragma unroll
        for (int j = k >> 1; j >= 8; j >>= 1) {
            const int m = j >> 3;
            const bool up  = (lane & m) != 0;
            const bool asc = (((lane << 3) & k) == 0);
            const bool keepMin = (up != asc);
            #pragma unroll
            for (int r = 0; r < 8; r++) {
                const float pv = __shfl_xor_sync(FULL_MASK, v[r], m);
                v[r] = keepMin ? fminf(v[r], pv) : fmaxf(v[r], pv);
            }
        }
        // In-register stages: j < 8 -> exchange regs r and r^j.
        #pragma unroll
        for (int j = ((k >> 1) < 4 ? (k >> 1) : 4); j >= 1; j >>= 1) {
            #pragma unroll
            for (int r = 0; r < 8; r++) {
                if ((r & j) == 0) {
                    const int p = r | j;
                    const bool asc = ((((lane << 3) | r) & k) == 0);
                    const float a = v[r], b = v[p];
                    const float lo = fminf(a, b), hi = fmaxf(a, b);
                    v[r] = asc ? lo : hi;
                    v[p] = asc ? hi : lo;
                }
            }
        }
    }
}

__global__ void ed_init_out(float* out) {
    if (threadIdx.x < EB) out[threadIdx.x] = 0.0f;
}

__global__ __launch_bounds__(256) void ed_kernel(
    const float* __restrict__ x1,
    const float* __restrict__ x2,
    float* __restrict__ out)
{
    // Per-warp column arrays, padded (phys(256)=288 < 292).
    __shared__ float st1[8][292];   // staged x1 col -> later exclusive prefix of sorted x2
    __shared__ float st2[8][292];   // staged x2 col -> later sorted x2 + INF sentinel

    const int b  = blockIdx.y;        // batch
    const int d0 = blockIdx.x << 3;   // first of 8 dims this block handles
    const int t  = threadIdx.x;
    const int w    = t >> 5;
    const int lane = t & 31;

    // ---- Stage: coalesced gmem -> smem (transpose to per-dim columns) ----
    const float* g1 = x1 + (size_t)b * EN * ED + d0;
    const float* g2 = x2 + (size_t)b * EN * ED + d0;
    #pragma unroll
    for (int it = 0; it < 8; it++) {
        const int flat = it * 256 + t;
        const int c = flat & 7;        // dim within group (contiguous in gmem)
        const int n = flat >> 3;       // sample index
        const int ph = n + (n >> 3);
        st1[c][ph] = g1[(size_t)n * ED + c];
        st2[c][ph] = g2[(size_t)n * ED + c];
    }
    __syncthreads();

    // ---- Warp-private: load column into registers (conflict-free) ----
    float v1[8], v2[8];
    #pragma unroll
    for (int r = 0; r < 8; r++) {
        const int i = (lane << 3) + r;
        v1[r] = st1[w][phys(i)];
        v2[r] = st2[w][phys(i)];
    }

    warp_sort256(v1, lane);
    warp_sort256(v2, lane);

    // ---- Prefix sums of sorted v2 ----
    float p[8];
    p[0] = v2[0];
    #pragma unroll
    for (int r = 1; r < 8; r++) p[r] = p[r - 1] + v2[r];
    float incl = p[7];
    #pragma unroll
    for (int off = 1; off < 32; off <<= 1) {
        const float nb = __shfl_up_sync(FULL_MASK, incl, off);
        if (lane >= off) incl += nb;
    }
    const float excl = incl - p[7];                       // sum of elems before this lane's block
    const float Ptot = __shfl_sync(FULL_MASK, incl, 31);  // total sum of v2

    // ---- Write sorted v2 + exclusive prefix back (each lane writes only
    //      the slots it read -> no cross-lane hazard before this point) ----
    #pragma unroll
    for (int r = 0; r < 8; r++) {
        const int i = (lane << 3) + r;
        st2[w][phys(i)] = v2[r];
        st1[w][phys(i)] = excl + (r ? p[r - 1] : 0.0f);
    }
    if (lane == 31) {
        st1[w][phys(EN)] = Ptot;
        st2[w][phys(EN)] = __int_as_float(0x7f800000);  // +INF sentinel
    }
    __syncwarp();

    // ---- Cross term via binary search + same-term closed form ----
    float acc = 0.0f;
    #pragma unroll
    for (int r = 0; r < 8; r++) {
        const float a = v1[r];
        int lo = 0, hi = EN;
        #pragma unroll
        for (int s = 0; s < 9; s++) {
            const int mid = (lo + hi) >> 1;
            const bool le = (st2[w][phys(mid)] <= a);
            lo = le ? mid + 1 : lo;
            hi = le ? hi : mid;
        }
        const float cross = a * (float)(2 * lo - EN) + Ptot - 2.0f * st1[w][phys(lo)];
        const int i = (lane << 3) + r;
        const float wt = (float)(2 * i - (EN - 1));
        acc += cross - wt * (v1[r] + v2[r]);
    }

    // ---- Warp reduce + one atomic per warp ----
    #pragma unroll
    for (int off = 16; off; off >>= 1)
        acc += __shfl_xor_sync(FULL_MASK, acc, off);
    if (lane == 0)
        atomicAdd(out + b, acc * (1.0f / (float)(EN * EN)));
}

extern "C" void kernel_launch(void* const* d_in, const int* in_sizes, int n_in,
                              void* d_out, int out_size)
{
    const float* x1 = (const float*)d_in[0];
    const float* x2 = (const float*)d_in[1];
    float* out = (float*)d_out;

    ed_init_out<<<1, 32>>>(out);
    dim3 grid(ED / 8, EB);   // (16, 16): 8 dims per block, one warp per dim
    ed_kernel<<<grid, 256>>>(x1, x2, out);
}